// round 13
// baseline (speedup 1.0000x reference)
#include <cuda_runtime.h>
#include <cuda_bf16.h>
#include <cstdint>

#define TV 16384
#define V_SZ 1024
#define T_SZ 16
#define B_SZ 256
#define JT 8                // W rows per block of work
#define NBLK (TV / JT)      // 2048 work blocks
#define GRID 444            // 148 SMs x 3 CTAs -> one persistent wave
#define NCONS 256           // consumer threads (one per batch element)
#define NTHREADS 288        // + 1 producer warp
#define QF 4096             // floats per quarter-row (4 t-slots)
#define QBYTES (QF * 4)     // 16 KB
#define NBUF 4              // ring stages (stage == quarter-in-row)
#define NQ (JT * 4)         // quarters per block

__device__ __forceinline__ void mbar_wait(uint32_t mbar, int parity) {
    asm volatile(
        "{\n\t"
        ".reg .pred P;\n\t"
        "WL_%=:\n\t"
        "mbarrier.try_wait.parity.acquire.cta.shared::cta.b64 P, [%0], %1, 0x989680;\n\t"
        "@P bra.uni WD_%=;\n\t"
        "bra.uni WL_%=;\n\t"
        "WD_%=:\n\t"
        "}" :: "r"(mbar), "r"(parity) : "memory");
}

// ---------------------------------------------------------------------------
// Persistent warp-specialized streaming. 444 resident CTAs each process
// blocks bid, bid+444, ... Each block = 8 W rows x all 256 batches.
// Producer warp streams dense 16KB quarters via cp.async.bulk through a
// 4-stage mbarrier ring; since each block is an even number of parity flips
// per stage, the ring runs continuously across blocks with NO drain and no
// extra sync. Consumers (thread = batch) gather 4 LDS per quarter and arrive
// empty via one lane per warp. Prologue (x indices, mbar init) paid once.
// ---------------------------------------------------------------------------
__global__ void __launch_bounds__(NTHREADS, 3) gather_sum_relu_kernel(
    const void* __restrict__ x_raw,     // [B, T] int64 or int32
    const float* __restrict__ W,        // [TV, TV] row-major
    const float* __restrict__ bias,     // [TV]
    float* __restrict__ out)            // [B, TV]
{
    extern __shared__ float buf[];                    // NBUF * QF floats
    __shared__ __align__(8) unsigned long long mb_full[NBUF];
    __shared__ __align__(8) unsigned long long mb_empty[NBUF];

    const int tid = threadIdx.x;
    const uint32_t buf_sa   = (uint32_t)__cvta_generic_to_shared(buf);
    const uint32_t full_sa  = (uint32_t)__cvta_generic_to_shared(mb_full);
    const uint32_t empty_sa = (uint32_t)__cvta_generic_to_shared(mb_empty);

    if (tid == 0) {
        #pragma unroll
        for (int i = 0; i < NBUF; i++) {
            asm volatile("mbarrier.init.shared.b64 [%0], 1;"
                         :: "r"(full_sa + i * 8) : "memory");   // producer arrive+tx
            asm volatile("mbarrier.init.shared.b64 [%0], 8;"
                         :: "r"(empty_sa + i * 8) : "memory");  // 8 consumer warps
        }
    }
    __syncthreads();                                  // barriers visible to all

    if (tid >= NCONS) {
        // ---------------- producer warp (lane 0 only) ----------------
        if (tid == NCONS) {
            for (int bid = blockIdx.x; bid < NBLK; bid += GRID) {
                const int j0 = bid * JT;
                for (int q = 0; q < NQ; q++) {
                    const int st = q & 3;             // stage == quarter-in-row
                    const int ph = ((q >> 2) & 1) ^ 1;
                    mbar_wait(empty_sa + st * 8, ph);
                    const uint32_t mb = full_sa + st * 8;
                    asm volatile("mbarrier.arrive.expect_tx.shared.b64 _, [%0], %1;"
                                 :: "r"(mb), "r"(QBYTES) : "memory");
                    const float* src = W + (size_t)(j0 + (q >> 2)) * TV + st * QF;
                    asm volatile(
                        "cp.async.bulk.shared::cta.global.mbarrier::complete_tx::bytes "
                        "[%0], [%1], %2, [%3];"
                        :: "r"(buf_sa + st * QBYTES), "l"(src), "r"(QBYTES), "r"(mb)
                        : "memory");
                }
            }
        }
        return;
    }

    // ---------------- consumer threads (thread = batch) ----------------
    // Gather indices (dtype-robust: int64 values in [0,V) look like (v,0)).
    const long long* x64 = (const long long*)x_raw;
    const int*       x32 = (const int*)x_raw;
    long long v64[T_SZ];
    bool ok64 = true;
    #pragma unroll
    for (int t = 0; t < T_SZ; t++) {
        v64[t] = x64[tid * T_SZ + t];
        if (v64[t] < 0 || v64[t] >= V_SZ) ok64 = false;
    }
    int c[T_SZ];   // float offset within the quarter that owns t-slot t
    #pragma unroll
    for (int t = 0; t < T_SZ; t++) {
        int xi = ok64 ? (int)v64[t] : x32[tid * T_SZ + t];
        c[t] = xi + (t & 3) * V_SZ;
    }

    const int lane = tid & 31;

    for (int bid = blockIdx.x; bid < NBLK; bid += GRID) {
        const int j0 = bid * JT;
        float acc[JT];

        #pragma unroll
        for (int r = 0; r < JT; r++) {
            float s = 0.f;
            #pragma unroll
            for (int q = 0; q < 4; q++) {
                mbar_wait(full_sa + q * 8, r & 1);
                const float* b = buf + q * QF;
                s += b[c[q * 4 + 0]] + b[c[q * 4 + 1]]
                   + b[c[q * 4 + 2]] + b[c[q * 4 + 3]];
                __syncwarp();
                if (lane == 0)
                    asm volatile("mbarrier.arrive.shared.b64 _, [%0];"
                                 :: "r"(empty_sa + q * 8) : "memory");
            }
            acc[r] = s;
        }

        // bias + relu + 32B contiguous store per thread (one DRAM sector)
        float rr[JT];
        #pragma unroll
        for (int jj = 0; jj < JT; jj++) {
            float v = acc[jj] + bias[j0 + jj];
            rr[jj] = v > 0.f ? v : 0.f;
        }
        float4* o = (float4*)(out + (size_t)tid * TV + j0);
        o[0] = make_float4(rr[0], rr[1], rr[2], rr[3]);
        o[1] = make_float4(rr[4], rr[5], rr[6], rr[7]);
    }
}

extern "C" void kernel_launch(void* const* d_in, const int* in_sizes, int n_in,
                              void* d_out, int out_size) {
    const void*  x    = d_in[0];                 // [256, 16] int64/int32
    const float* W    = (const float*)d_in[1];   // [16384, 16384]
    const float* bias = (const float*)d_in[2];   // [16384]
    float* out = (float*)d_out;                  // [256, 16384]

    const int smem_bytes = NBUF * QBYTES;        // 64 KB dynamic -> 3 CTAs/SM
    static bool attr_set = false;
    if (!attr_set) {
        cudaFuncSetAttribute(gather_sum_relu_kernel,
                             cudaFuncAttributeMaxDynamicSharedMemorySize, smem_bytes);
        attr_set = true;
    }

    gather_sum_relu_kernel<<<GRID, NTHREADS, smem_bytes>>>(x, W, bias, out);
}